// round 1
// baseline (speedup 1.0000x reference)
#include <cuda_runtime.h>
#include <cuda_bf16.h>
#include <math.h>

#define HIDDEN 2048
#define VOCAB  50257

// Scratch (allocation-free rule: __device__ globals)
__device__ float g_hnew[HIDDEN];
__device__ float g_logits[VOCAB];
__device__ float g_lse[1];

__device__ __forceinline__ float sigmoidf_(float x) {
    return 1.0f / (1.0f + __expf(-x));
}

__device__ __forceinline__ float warp_sum(float v) {
    #pragma unroll
    for (int o = 16; o > 0; o >>= 1) v += __shfl_xor_sync(0xFFFFFFFFu, v, o);
    return v;
}

// ---------------------------------------------------------------------------
// Kernel 1: fused embed+ReLU + GRU cell. One warp per hidden unit j.
// Block = 256 threads (8 warps) -> 8 hidden units per block, grid = 256.
// ---------------------------------------------------------------------------
__global__ __launch_bounds__(256) void gru_kernel(
    const int* __restrict__ token,
    const float* __restrict__ hidden,
    const float* __restrict__ emb,
    const float* __restrict__ w_ih,
    const float* __restrict__ w_hh,
    const float* __restrict__ b_ih,
    const float* __restrict__ b_hh,
    float* __restrict__ hnew_out)   // may be nullptr
{
    __shared__ float sx[HIDDEN];   // relu(emb[token])
    __shared__ float sh[HIDDEN];   // hidden

    const int t = token[0];
    const float4* e4 = (const float4*)(emb + (size_t)t * HIDDEN);
    const float4* h4 = (const float4*)hidden;
    for (int i = threadIdx.x; i < HIDDEN / 4; i += blockDim.x) {
        float4 e = e4[i];
        e.x = fmaxf(e.x, 0.0f); e.y = fmaxf(e.y, 0.0f);
        e.z = fmaxf(e.z, 0.0f); e.w = fmaxf(e.w, 0.0f);
        ((float4*)sx)[i] = e;
        ((float4*)sh)[i] = h4[i];
    }
    __syncthreads();

    const int warp = threadIdx.x >> 5;
    const int lane = threadIdx.x & 31;
    const int j = blockIdx.x * 8 + warp;   // hidden unit index, < 2048

    const float4* wir = (const float4*)(w_ih + (size_t)j * HIDDEN);
    const float4* wiz = (const float4*)(w_ih + (size_t)(HIDDEN + j) * HIDDEN);
    const float4* win = (const float4*)(w_ih + (size_t)(2 * HIDDEN + j) * HIDDEN);
    const float4* whr = (const float4*)(w_hh + (size_t)j * HIDDEN);
    const float4* whz = (const float4*)(w_hh + (size_t)(HIDDEN + j) * HIDDEN);
    const float4* whn = (const float4*)(w_hh + (size_t)(2 * HIDDEN + j) * HIDDEN);

    float a_ir = 0.f, a_iz = 0.f, a_in = 0.f;
    float a_hr = 0.f, a_hz = 0.f, a_hn = 0.f;

    #pragma unroll
    for (int i = lane; i < HIDDEN / 4; i += 32) {
        float4 xv = ((const float4*)sx)[i];
        float4 hv = ((const float4*)sh)[i];
        float4 w;
        w = wir[i]; a_ir += w.x*xv.x + w.y*xv.y + w.z*xv.z + w.w*xv.w;
        w = wiz[i]; a_iz += w.x*xv.x + w.y*xv.y + w.z*xv.z + w.w*xv.w;
        w = win[i]; a_in += w.x*xv.x + w.y*xv.y + w.z*xv.z + w.w*xv.w;
        w = whr[i]; a_hr += w.x*hv.x + w.y*hv.y + w.z*hv.z + w.w*hv.w;
        w = whz[i]; a_hz += w.x*hv.x + w.y*hv.y + w.z*hv.z + w.w*hv.w;
        w = whn[i]; a_hn += w.x*hv.x + w.y*hv.y + w.z*hv.z + w.w*hv.w;
    }
    a_ir = warp_sum(a_ir); a_iz = warp_sum(a_iz); a_in = warp_sum(a_in);
    a_hr = warp_sum(a_hr); a_hz = warp_sum(a_hz); a_hn = warp_sum(a_hn);

    if (lane == 0) {
        float i_r = a_ir + b_ih[j];
        float i_z = a_iz + b_ih[HIDDEN + j];
        float i_n = a_in + b_ih[2 * HIDDEN + j];
        float h_r = a_hr + b_hh[j];
        float h_z = a_hz + b_hh[HIDDEN + j];
        float h_n = a_hn + b_hh[2 * HIDDEN + j];
        float r = sigmoidf_(i_r + h_r);
        float z = sigmoidf_(i_z + h_z);
        float n = tanhf(i_n + r * h_n);
        float hn_val = (1.0f - z) * n + z * sh[j];
        g_hnew[j] = hn_val;
        if (hnew_out) hnew_out[j] = hn_val;
    }
}

// ---------------------------------------------------------------------------
// Kernel 2: logits = w_out @ h_new + b_out. One warp per vocab row.
// Block = 256 threads (8 warps/rows), grid = ceil(V/8).
// ---------------------------------------------------------------------------
__global__ __launch_bounds__(256) void logits_kernel(
    const float* __restrict__ w_out,
    const float* __restrict__ b_out)
{
    __shared__ float sh[HIDDEN];
    for (int i = threadIdx.x; i < HIDDEN; i += blockDim.x) sh[i] = g_hnew[i];
    __syncthreads();

    const int warp = threadIdx.x >> 5;
    const int lane = threadIdx.x & 31;
    const int v = blockIdx.x * 8 + warp;
    if (v >= VOCAB) return;

    const float4* w = (const float4*)(w_out + (size_t)v * HIDDEN);
    float acc = 0.f;
    #pragma unroll
    for (int i = lane; i < HIDDEN / 4; i += 32) {
        float4 wv = w[i];
        float4 hv = ((const float4*)sh)[i];
        acc += wv.x*hv.x + wv.y*hv.y + wv.z*hv.z + wv.w*hv.w;
    }
    acc = warp_sum(acc);
    if (lane == 0) g_logits[v] = acc + b_out[v];
}

// ---------------------------------------------------------------------------
// Kernel 3: single-block max + log-sum-exp over V logits.
// ---------------------------------------------------------------------------
__global__ __launch_bounds__(1024) void lse_kernel()
{
    __shared__ float sred[32];
    const int tid = threadIdx.x;
    const int lane = tid & 31, warp = tid >> 5;

    // pass 1: max
    float m = -INFINITY;
    for (int i = tid; i < VOCAB; i += 1024) m = fmaxf(m, g_logits[i]);
    #pragma unroll
    for (int o = 16; o > 0; o >>= 1) m = fmaxf(m, __shfl_xor_sync(0xFFFFFFFFu, m, o));
    if (lane == 0) sred[warp] = m;
    __syncthreads();
    if (warp == 0) {
        float mm = (lane < 32) ? sred[lane] : -INFINITY;
        #pragma unroll
        for (int o = 16; o > 0; o >>= 1) mm = fmaxf(mm, __shfl_xor_sync(0xFFFFFFFFu, mm, o));
        if (lane == 0) sred[0] = mm;
    }
    __syncthreads();
    const float gmax = sred[0];
    __syncthreads();

    // pass 2: sum of exp
    float s = 0.f;
    for (int i = tid; i < VOCAB; i += 1024) s += __expf(g_logits[i] - gmax);
    s = warp_sum(s);
    if (lane == 0) sred[warp] = s;
    __syncthreads();
    if (warp == 0) {
        float ss = (lane < 32) ? sred[lane] : 0.f;
        ss = warp_sum(ss);
        if (lane == 0) g_lse[0] = gmax + logf(ss);
    }
}

// ---------------------------------------------------------------------------
// Kernel 4: out[i] = logits[i] - lse
// ---------------------------------------------------------------------------
__global__ __launch_bounds__(256) void finalize_kernel(float* __restrict__ out)
{
    const float lse = g_lse[0];
    int i = blockIdx.x * blockDim.x + threadIdx.x;
    if (i < VOCAB) out[i] = g_logits[i] - lse;
}

extern "C" void kernel_launch(void* const* d_in, const int* in_sizes, int n_in,
                              void* d_out, int out_size) {
    const int*   token  = (const int*)  d_in[0];
    const float* hidden = (const float*)d_in[1];
    const float* emb    = (const float*)d_in[2];
    const float* w_ih   = (const float*)d_in[3];
    const float* w_hh   = (const float*)d_in[4];
    const float* b_ih   = (const float*)d_in[5];
    const float* b_hh   = (const float*)d_in[6];
    const float* w_out  = (const float*)d_in[7];
    const float* b_out  = (const float*)d_in[8];
    float* out = (float*)d_out;

    float* hnew_out = (out_size >= VOCAB + HIDDEN) ? (out + VOCAB) : nullptr;

    gru_kernel<<<HIDDEN / 8, 256>>>(token, hidden, emb, w_ih, w_hh, b_ih, b_hh, hnew_out);
    logits_kernel<<<(VOCAB + 7) / 8, 256>>>(w_out, b_out);
    lse_kernel<<<1, 1024>>>();
    finalize_kernel<<<(VOCAB + 255) / 256, 256>>>(out);
}